// round 8
// baseline (speedup 1.0000x reference)
#include <cuda_runtime.h>
#include <stdint.h>

#define BB 384
#define DD 256
#define MARGIN_F 0.2f

// RNG field layout for jax.random.gumbel(key(42), (B,B,B)):
//   0 = legacy split-halves                      [R2: rel 2.25e-2 -> fully wrong]
//   1 = partitionable, x=(0,m), bits = o1        [R1: rel 4.4e-3  -> wrong (lucky-low draw)]
//   2 = partitionable, x=(0,m), bits = o0        [R7: rel 3.5e-3  -> wrong (lucky-low draw)]
//   5 = partitionable, x=(0,m), bits = o0 ^ o1   [this round: matches jax prng.py
//       _threefry_random_bits_partitionable bit_width<=32 path: bits1 ^ bits2]
//   6 = partitionable, x=(m,0), bits = o0 ^ o1   [fallback candidate]
#define JAX_RNG_MODE 5

__device__ float g_bsum[BB];
__device__ int   g_bcnt[BB];

__device__ __forceinline__ uint32_t rotl32(uint32_t x, uint32_t r) {
    return (x << r) | (x >> (32u - r));
}

__device__ __forceinline__ void threefry2x32(uint32_t k0, uint32_t k1,
                                             uint32_t x0, uint32_t x1,
                                             uint32_t& o0, uint32_t& o1) {
    const uint32_t ks2 = 0x1BD11BDAu ^ k0 ^ k1;
    x0 += k0; x1 += k1;
#define TF_R(r) { x0 += x1; x1 = rotl32(x1, (r)); x1 ^= x0; }
    TF_R(13u) TF_R(15u) TF_R(26u) TF_R(6u)
    x0 += k1;  x1 += ks2 + 1u;
    TF_R(17u) TF_R(29u) TF_R(16u) TF_R(24u)
    x0 += ks2; x1 += k0 + 2u;
    TF_R(13u) TF_R(15u) TF_R(26u) TF_R(6u)
    x0 += k0;  x1 += k1 + 3u;
    TF_R(17u) TF_R(29u) TF_R(16u) TF_R(24u)
    x0 += k1;  x1 += ks2 + 4u;
    TF_R(13u) TF_R(15u) TF_R(26u) TF_R(6u)
    x0 += ks2; x1 += k0 + 5u;
#undef TF_R
    o0 = x0; o1 = x1;
}

// Gumbel(0,1) sample at flat index m of the (B,B,B) field, jax.random.key(42) -> key=(0,42).
__device__ __forceinline__ float gumbel_at(uint32_t m) {
    uint32_t o0, o1, bits;
#if JAX_RNG_MODE == 0
    const uint32_t HALF = (uint32_t)(((unsigned long long)BB * BB * BB) / 2ull);
    if (m < HALF) { threefry2x32(0u, 42u, m, m + HALF, o0, o1); bits = o0; }
    else          { threefry2x32(0u, 42u, m - HALF, m, o0, o1); bits = o1; }
#elif JAX_RNG_MODE == 1
    threefry2x32(0u, 42u, 0u, m, o0, o1); bits = o1;
#elif JAX_RNG_MODE == 2
    threefry2x32(0u, 42u, 0u, m, o0, o1); bits = o0;
#elif JAX_RNG_MODE == 5
    threefry2x32(0u, 42u, 0u, m, o0, o1); bits = o0 ^ o1;
#else  // 6
    threefry2x32(0u, 42u, m, 0u, o0, o1); bits = o0 ^ o1;
#endif
    // uniform(minval=tiny, maxval=1): f in [0,1), u = max(tiny, f*(1-tiny)+tiny); (1-tiny)==1 fp32
    const uint32_t fb = (bits >> 9) | 0x3f800000u;
    const float f = __uint_as_float(fb) - 1.0f;
    const float TINY = 1.17549435e-38f;
    const float u = fmaxf(TINY, f + TINY);
    // -log(-log(u)); double internally to stay within ~1ulp of XLA's f32 log
    double lu = log((double)u);
    return (float)(-log(-lu));
}

__global__ __launch_bounds__(256) void triplet_anchor_kernel(
    const float* __restrict__ feat,
    const int*   __restrict__ labels,
    const int*   __restrict__ epoch_p)
{
    const int i = blockIdx.x;
    const int t = threadIdx.x;
    const int w = t >> 5;
    const int l = t & 31;

    __shared__ float srow[DD];        // features[i]
    __shared__ float sch[8 * DD];     // 8-row feature chunk
    __shared__ float sdist[BB];       // dist row i
    __shared__ int   slab[BB];
    __shared__ float rbest[256];
    __shared__ int   ridx[256];
    __shared__ int   rany[256];

    srow[t] = feat[i * DD + t];
    slab[t] = labels[t];
    if (t + 256 < BB) slab[t + 256] = labels[t + 256];

    // ---- Phase 1: dist[i, :] into sdist (48 chunks x 8 rows, one warp per row) ----
    for (int jc = 0; jc < BB / 8; jc++) {
        __syncthreads();
        const float* src = feat + jc * 8 * DD;
#pragma unroll
        for (int q = 0; q < 8; q++) sch[t + 256 * q] = src[t + 256 * q];
        __syncthreads();
        float s = 0.0f;
#pragma unroll
        for (int q = 0; q < 8; q++) {
            const int d = l + 32 * q;
            const float df = srow[d] - sch[w * DD + d];
            s = fmaf(df, df, s);
        }
#pragma unroll
        for (int o = 16; o > 0; o >>= 1) s += __shfl_xor_sync(0xffffffffu, s, o);
        if (l == 0) sdist[jc * 8 + w] = sqrtf(fmaxf(s, 1e-11f));
    }
    __syncthreads();

    // ---- Phase 2: loop positive partners j > i with same label ----
    const int  myl      = slab[i];
    const bool semimode = (*epoch_p) > 3;
    float acc = 0.0f;
    int   cnt = 0;

    for (int j = i + 1; j < BB; j++) {
        if (slab[j] != myl) continue;  // uniform across block
        const float dij = sdist[j];
        const uint32_t base = ((uint32_t)i * BB + (uint32_t)j) * BB;

        float best = -3.0e38f;
        int   bidx = BB;
        int   any  = 0;
        for (int k = t; k < BB; k += 256) {
            if (slab[k] == myl) continue;       // need a negative
            const float dik = sdist[k];
            float basescore;
            if (semimode) {
                if (!(dik > dij && dik < dij + MARGIN_F)) continue;  // semi-hard window
                basescore = (float)(-log((double)dik));
            } else {
                basescore = 0.0f;
            }
            any = 1;
            const float sc = basescore + gumbel_at(base + (uint32_t)k);
            if (sc > best) { best = sc; bidx = k; }  // '>' keeps first index on tie
        }
        rbest[t] = best; ridx[t] = bidx; rany[t] = any;
        __syncthreads();
#pragma unroll
        for (int o = 128; o > 0; o >>= 1) {
            if (t < o) {
                const float ob = rbest[t + o];
                const int   oi = ridx[t + o];
                if (ob > rbest[t] || (ob == rbest[t] && oi < ridx[t])) {
                    rbest[t] = ob; ridx[t] = oi;
                }
                rany[t] |= rany[t + o];
            }
            __syncthreads();
        }
        if (t == 0 && rany[0]) {
            const float nd = sdist[ridx[0]];
            acc += fmaxf(0.0f, dij - nd + MARGIN_F);
            cnt += 1;
        }
        __syncthreads();  // protect reduce arrays before next j
    }

    if (t == 0) { g_bsum[i] = acc; g_bcnt[i] = cnt; }
}

__global__ __launch_bounds__(512) void triplet_finalize_kernel(float* __restrict__ out)
{
    __shared__ float ss[512];
    __shared__ int   sc[512];
    const int t = threadIdx.x;
    float s = 0.0f; int c = 0;
    if (t < BB) { s = g_bsum[t]; c = g_bcnt[t]; }
    ss[t] = s; sc[t] = c;
    __syncthreads();
#pragma unroll
    for (int o = 256; o > 0; o >>= 1) {
        if (t < o) { ss[t] += ss[t + o]; sc[t] += sc[t + o]; }
        __syncthreads();
    }
    if (t == 0) out[0] = (sc[0] > 0) ? (ss[0] / (float)sc[0]) : 0.0f;
}

extern "C" void kernel_launch(void* const* d_in, const int* in_sizes, int n_in,
                              void* d_out, int out_size)
{
    const float* feat   = (const float*)d_in[0];
    const int*   labels = (const int*)d_in[1];
    const int*   epoch  = (const int*)d_in[2];
    float*       out    = (float*)d_out;
    (void)in_sizes; (void)n_in; (void)out_size;

    triplet_anchor_kernel<<<BB, 256>>>(feat, labels, epoch);
    triplet_finalize_kernel<<<1, 512>>>(out);
}

// round 10
// speedup vs baseline: 4.9556x; 4.9556x over previous
#include <cuda_runtime.h>
#include <stdint.h>

#define BB 384
#define DD 256
#define MARGIN_F 0.2f
#define NWARP 8
#define FULLMASK 0xffffffffu

// RNG layout (settled R8): jax partitionable threefry, counts=(0,m), bits = o0 ^ o1.

__device__ float g_bsum[BB];
__device__ int   g_bcnt[BB];

__device__ __forceinline__ uint32_t rotl32(uint32_t x, uint32_t r) {
    return (x << r) | (x >> (32u - r));
}

__device__ __forceinline__ void threefry2x32(uint32_t k0, uint32_t k1,
                                             uint32_t x0, uint32_t x1,
                                             uint32_t& o0, uint32_t& o1) {
    const uint32_t ks2 = 0x1BD11BDAu ^ k0 ^ k1;
    x0 += k0; x1 += k1;
#define TF_R(r) { x0 += x1; x1 = rotl32(x1, (r)); x1 ^= x0; }
    TF_R(13u) TF_R(15u) TF_R(26u) TF_R(6u)
    x0 += k1;  x1 += ks2 + 1u;
    TF_R(17u) TF_R(29u) TF_R(16u) TF_R(24u)
    x0 += ks2; x1 += k0 + 2u;
    TF_R(13u) TF_R(15u) TF_R(26u) TF_R(6u)
    x0 += k0;  x1 += k1 + 3u;
    TF_R(17u) TF_R(29u) TF_R(16u) TF_R(24u)
    x0 += k1;  x1 += ks2 + 4u;
    TF_R(13u) TF_R(15u) TF_R(26u) TF_R(6u)
    x0 += ks2; x1 += k0 + 5u;
#undef TF_R
    o0 = x0; o1 = x1;
}

// Accurate (~1-2 ulp) fp32 natural log for x > 0. No FP64, independent of fast-math flags.
__device__ __forceinline__ float flog_pos(float x) {
    int ix = __float_as_int(x);
    int e = 0;
    if (ix < 0x00800000) {               // subnormal (x > 0 assumed)
        x *= 8388608.0f;                 // 2^23
        ix = __float_as_int(x);
        e = -23;
    }
    e += ((ix >> 23) & 0xff) - 127;
    ix = (ix & 0x007fffff) | 0x3f800000;
    float m = __int_as_float(ix);        // [1, 2)
    if (m > 1.4142135f) { m *= 0.5f; e += 1; }   // [0.7071, 1.4142)
    const float f  = m - 1.0f;
    const float z  = f / (f + 2.0f);     // |z| <= 0.1716
    const float z2 = z * z;
    // atanh(z)/z - 1 = z2/3 + z4/5 + z6/7 + z8/9 (+O(2e-9) rel)
    float poly = fmaf(z2, fmaf(z2, fmaf(z2, 0.11111111f, 0.14285714f), 0.2f), 0.33333333f);
    float lm = fmaf(2.0f * z * z2, poly, 2.0f * z);   // log(m)
    const float fe = (float)e;
    float r = fmaf(fe, -2.12194440e-4f, lm);  // ln2_lo
    return  fmaf(fe,  0.693359375f,   r);     // ln2_hi (exact product)
}

// Gumbel(0,1) at flat index m of the (B,B,B) field, key=(0,42).
__device__ __forceinline__ float gumbel_at(uint32_t m) {
    uint32_t o0, o1;
    threefry2x32(0u, 42u, 0u, m, o0, o1);
    const uint32_t bits = o0 ^ o1;
    const uint32_t fb = (bits >> 9) | 0x3f800000u;
    const float f = __uint_as_float(fb) - 1.0f;
    const float TINY = 1.17549435e-38f;
    const float u = fmaxf(TINY, f + TINY);
    const float w = -flog_pos(u);        // > 0 strictly (u < 1)
    return -flog_pos(w);
}

__global__ __launch_bounds__(256) void triplet_anchor_kernel(
    const float* __restrict__ feat,
    const int*   __restrict__ labels,
    const int*   __restrict__ epoch_p)
{
    const int i = blockIdx.x;
    const int t = threadIdx.x;
    const int w = t >> 5;
    const int l = t & 31;

    __shared__ float sdist[BB];
    __shared__ int   slab[BB];
    __shared__ int   plist[BB];
    __shared__ int   pcount;
    __shared__ float wacc[NWARP];
    __shared__ int   wcnt[NWARP];

    slab[t] = labels[t];
    if (t + 256 < BB) slab[t + 256] = labels[t + 256];

    // anchor row i in registers (lane l holds dims l, l+32, ..., l+224)
    float srow[8];
#pragma unroll
    for (int q = 0; q < 8; q++) srow[q] = feat[i * DD + l + 32 * q];

    __syncthreads();  // slab visible

    // ---- Phase 1: warp w computes dist rows j = w*48 .. w*48+47, 2-row interleave ----
    {
        const int j0 = w * 48;
        for (int jj = 0; jj < 48; jj += 2) {
            const float* fa = feat + (j0 + jj)     * DD;
            const float* fb = feat + (j0 + jj + 1) * DD;
            float sa = 0.0f, sb = 0.0f;
#pragma unroll
            for (int q = 0; q < 8; q++) {
                const int d = l + 32 * q;
                const float da = srow[q] - fa[d];
                const float db = srow[q] - fb[d];
                sa = fmaf(da, da, sa);
                sb = fmaf(db, db, sb);
            }
#pragma unroll
            for (int o = 16; o > 0; o >>= 1) {
                sa += __shfl_xor_sync(FULLMASK, sa, o);
                sb += __shfl_xor_sync(FULLMASK, sb, o);
            }
            if (l == 0) {
                sdist[j0 + jj]     = sqrtf(fmaxf(sa, 1e-11f));
                sdist[j0 + jj + 1] = sqrtf(fmaxf(sb, 1e-11f));
            }
        }
    }

    // ---- Positive-j list (warp 0, deterministic increasing-j order) ----
    const int myl = slab[i];
    if (w == 0) {
        int cnt = 0;
#pragma unroll
        for (int c = 0; c < BB / 32; c++) {
            const int j = c * 32 + l;
            const bool p = (j > i) && (slab[j] == myl);
            const unsigned mask = __ballot_sync(FULLMASK, p);
            if (p) plist[cnt + __popc(mask & ((1u << l) - 1u))] = j;
            cnt += __popc(mask);
        }
        if (l == 0) pcount = cnt;
    }
    __syncthreads();  // sdist + plist visible

    // ---- Phase 2: warp per positive pair ----
    const bool semimode = (*epoch_p) > 3;
    const int np = pcount;
    float acc = 0.0f;
    int   cnt = 0;

    for (int p = w; p < np; p += NWARP) {
        const int j = plist[p];
        const float dij = sdist[j];
        const uint32_t base = ((uint32_t)i * BB + (uint32_t)j) * BB;

        float best = -3.0e38f;
        int   bidx = BB;
        bool  any  = false;
#pragma unroll 2
        for (int q = 0; q < BB / 32; q++) {
            const int k = l + 32 * q;
            const bool neg = (slab[k] != myl);
            const float dik = sdist[k];
            bool act;
            if (semimode) act = neg && (dik > dij) && (dik < dij + MARGIN_F);
            else          act = neg;
            if (act) {
                float sc = gumbel_at(base + (uint32_t)k);
                if (semimode) sc -= flog_pos(dik);
                any = true;
                if (sc > best) { best = sc; bidx = k; }  // '>' keeps first index per lane
            }
        }
        const unsigned anym = __ballot_sync(FULLMASK, any);
#pragma unroll
        for (int o = 16; o > 0; o >>= 1) {
            const float ob = __shfl_xor_sync(FULLMASK, best, o);
            const int   oi = __shfl_xor_sync(FULLMASK, bidx, o);
            if (ob > best || (ob == best && oi < bidx)) { best = ob; bidx = oi; }
        }
        if (l == 0 && anym) {
            acc += fmaxf(0.0f, dij - sdist[bidx] + MARGIN_F);
            cnt += 1;
        }
    }

    if (l == 0) { wacc[w] = acc; wcnt[w] = cnt; }
    __syncthreads();
    if (t == 0) {
        float a = 0.0f; int c = 0;
#pragma unroll
        for (int q = 0; q < NWARP; q++) { a += wacc[q]; c += wcnt[q]; }
        g_bsum[i] = a; g_bcnt[i] = c;
    }
}

__global__ __launch_bounds__(512) void triplet_finalize_kernel(float* __restrict__ out)
{
    __shared__ float ss[512];
    __shared__ int   sc[512];
    const int t = threadIdx.x;
    float s = 0.0f; int c = 0;
    if (t < BB) { s = g_bsum[t]; c = g_bcnt[t]; }
    ss[t] = s; sc[t] = c;
    __syncthreads();
#pragma unroll
    for (int o = 256; o > 0; o >>= 1) {
        if (t < o) { ss[t] += ss[t + o]; sc[t] += sc[t + o]; }
        __syncthreads();
    }
    if (t == 0) out[0] = (sc[0] > 0) ? (ss[0] / (float)sc[0]) : 0.0f;
}

extern "C" void kernel_launch(void* const* d_in, const int* in_sizes, int n_in,
                              void* d_out, int out_size)
{
    const float* feat   = (const float*)d_in[0];
    const int*   labels = (const int*)d_in[1];
    const int*   epoch  = (const int*)d_in[2];
    float*       out    = (float*)d_out;
    (void)in_sizes; (void)n_in; (void)out_size;

    triplet_anchor_kernel<<<BB, 256>>>(feat, labels, epoch);
    triplet_finalize_kernel<<<1, 512>>>(out);
}

// round 15
// speedup vs baseline: 5.8973x; 1.1900x over previous
#include <cuda_runtime.h>
#include <stdint.h>

#define BB 384
#define DD 256
#define MARGIN_F 0.2f
#define NWARP 8
#define FULLMASK 0xffffffffu

// RNG layout (settled R8): jax partitionable threefry, counts=(0,m), bits = o0 ^ o1.

__device__ float g_dist[BB * BB];
__device__ float g_bsum[BB];
__device__ int   g_bcnt[BB];
__device__ int   g_arrive = 0;

__device__ __forceinline__ uint32_t rotl32(uint32_t x, uint32_t r) {
    return (x << r) | (x >> (32u - r));
}

__device__ __forceinline__ void threefry2x32(uint32_t k0, uint32_t k1,
                                             uint32_t x0, uint32_t x1,
                                             uint32_t& o0, uint32_t& o1) {
    const uint32_t ks2 = 0x1BD11BDAu ^ k0 ^ k1;
    x0 += k0; x1 += k1;
#define TF_R(r) { x0 += x1; x1 = rotl32(x1, (r)); x1 ^= x0; }
    TF_R(13u) TF_R(15u) TF_R(26u) TF_R(6u)
    x0 += k1;  x1 += ks2 + 1u;
    TF_R(17u) TF_R(29u) TF_R(16u) TF_R(24u)
    x0 += ks2; x1 += k0 + 2u;
    TF_R(13u) TF_R(15u) TF_R(26u) TF_R(6u)
    x0 += k0;  x1 += k1 + 3u;
    TF_R(17u) TF_R(29u) TF_R(16u) TF_R(24u)
    x0 += k1;  x1 += ks2 + 4u;
    TF_R(13u) TF_R(15u) TF_R(26u) TF_R(6u)
    x0 += ks2; x1 += k0 + 5u;
#undef TF_R
    o0 = x0; o1 = x1;
}

// Accurate (~1-2 ulp) fp32 natural log for x > 0. No FP64, fast-math independent.
__device__ __forceinline__ float flog_pos(float x) {
    int ix = __float_as_int(x);
    int e = 0;
    if (ix < 0x00800000) {               // subnormal (x > 0 assumed)
        x *= 8388608.0f;                 // 2^23
        ix = __float_as_int(x);
        e = -23;
    }
    e += ((ix >> 23) & 0xff) - 127;
    ix = (ix & 0x007fffff) | 0x3f800000;
    float m = __int_as_float(ix);        // [1, 2)
    if (m > 1.4142135f) { m *= 0.5f; e += 1; }   // [0.7071, 1.4142)
    const float f  = m - 1.0f;
    const float z  = f / (f + 2.0f);
    const float z2 = z * z;
    float poly = fmaf(z2, fmaf(z2, fmaf(z2, 0.11111111f, 0.14285714f), 0.2f), 0.33333333f);
    float lm = fmaf(2.0f * z * z2, poly, 2.0f * z);
    const float fe = (float)e;
    float r = fmaf(fe, -2.12194440e-4f, lm);
    return  fmaf(fe,  0.693359375f,   r);
}

// Gumbel(0,1) at flat index m of the (B,B,B) field, key=(0,42).
__device__ __forceinline__ float gumbel_at(uint32_t m) {
    uint32_t o0, o1;
    threefry2x32(0u, 42u, 0u, m, o0, o1);
    const uint32_t bits = o0 ^ o1;
    const uint32_t fb = (bits >> 9) | 0x3f800000u;
    const float f = __uint_as_float(fb) - 1.0f;
    const float TINY = 1.17549435e-38f;
    const float u = fmaxf(TINY, f + TINY);
    const float w = -flog_pos(u);
    return -flog_pos(w);
}

// ---------------------------------------------------------------------------
// Kernel A: dist matrix. grid (48, 3); block 256.
// CTA = 8 anchors (one per warp), 128-row tile staged via SMEM in 32-row chunks.
// Per-lane accumulation order identical to the proven R10 kernel -> bit-identical dist.
// ---------------------------------------------------------------------------
__global__ __launch_bounds__(256) void dist_kernel(const float* __restrict__ feat)
{
    __shared__ float sch[32 * DD];   // 32 KB chunk

    const int t = threadIdx.x;
    const int w = t >> 5;
    const int l = t & 31;
    const int a = blockIdx.x * NWARP + w;       // anchor for this warp
    const int rbase = blockIdx.y * 128;         // row tile

    float srow[8];
#pragma unroll
    for (int q = 0; q < 8; q++) srow[q] = feat[a * DD + l + 32 * q];

    for (int ch = 0; ch < 4; ch++) {
        const int r0 = rbase + ch * 32;
        __syncthreads();
        // stage 32 rows (8192 floats) coalesced as float4
        const float4* src = (const float4*)(feat + r0 * DD);
        float4* dst = (float4*)sch;
        for (int idx = t; idx < 32 * DD / 4; idx += 256) dst[idx] = src[idx];
        __syncthreads();

        for (int jj = 0; jj < 32; jj += 2) {
            const float* fa = sch + jj * DD;
            const float* fb = fa + DD;
            float sa = 0.0f, sb = 0.0f;
#pragma unroll
            for (int q = 0; q < 8; q++) {
                const int d = l + 32 * q;
                const float da = srow[q] - fa[d];
                const float db = srow[q] - fb[d];
                sa = fmaf(da, da, sa);
                sb = fmaf(db, db, sb);
            }
#pragma unroll
            for (int o = 16; o > 0; o >>= 1) {
                sa += __shfl_xor_sync(FULLMASK, sa, o);
                sb += __shfl_xor_sync(FULLMASK, sb, o);
            }
            if (l == 0) {
                g_dist[a * BB + r0 + jj]     = sqrtf(fmaxf(sa, 1e-11f));
                g_dist[a * BB + r0 + jj + 1] = sqrtf(fmaxf(sb, 1e-11f));
            }
        }
    }
}

// ---------------------------------------------------------------------------
// Kernel B: per-anchor pair work + folded finalize (last CTA reduces).
// ---------------------------------------------------------------------------
__global__ __launch_bounds__(256) void pair_kernel(
    const int* __restrict__ labels,
    const int* __restrict__ epoch_p,
    float*     __restrict__ out)
{
    const int i = blockIdx.x;
    const int t = threadIdx.x;
    const int w = t >> 5;
    const int l = t & 31;

    __shared__ float sdist[BB];
    __shared__ int   slab[BB];
    __shared__ int   plist[BB];
    __shared__ int   pcount;
    __shared__ float wacc[NWARP];
    __shared__ int   wcnt[NWARP];
    __shared__ int   slast;

    sdist[t] = g_dist[i * BB + t];
    slab[t]  = labels[t];
    if (t < BB - 256) {
        sdist[t + 256] = g_dist[i * BB + t + 256];
        slab[t + 256]  = labels[t + 256];
    }
    __syncthreads();

    // positive-j list (warp 0, deterministic increasing-j order)
    const int myl = slab[i];
    if (w == 0) {
        int cnt = 0;
#pragma unroll
        for (int c = 0; c < BB / 32; c++) {
            const int j = c * 32 + l;
            const bool p = (j > i) && (slab[j] == myl);
            const unsigned mask = __ballot_sync(FULLMASK, p);
            if (p) plist[cnt + __popc(mask & ((1u << l) - 1u))] = j;
            cnt += __popc(mask);
        }
        if (l == 0) pcount = cnt;
    }
    __syncthreads();

    const bool semimode = (*epoch_p) > 3;
    const int np = pcount;
    float acc = 0.0f;
    int   cnt = 0;

    for (int p = w; p < np; p += NWARP) {
        const int j = plist[p];
        const float dij = sdist[j];
        const uint32_t base = ((uint32_t)i * BB + (uint32_t)j) * BB;

        float best = -3.0e38f;
        int   bidx = BB;
        bool  any  = false;
#pragma unroll 2
        for (int q = 0; q < BB / 32; q++) {
            const int k = l + 32 * q;
            const bool neg = (slab[k] != myl);
            const float dik = sdist[k];
            bool act;
            if (semimode) act = neg && (dik > dij) && (dik < dij + MARGIN_F);
            else          act = neg;
            if (act) {
                float sc = gumbel_at(base + (uint32_t)k);
                if (semimode) sc -= flog_pos(dik);
                any = true;
                if (sc > best) { best = sc; bidx = k; }  // '>' keeps first index per lane
            }
        }
        const unsigned anym = __ballot_sync(FULLMASK, any);
#pragma unroll
        for (int o = 16; o > 0; o >>= 1) {
            const float ob = __shfl_xor_sync(FULLMASK, best, o);
            const int   oi = __shfl_xor_sync(FULLMASK, bidx, o);
            if (ob > best || (ob == best && oi < bidx)) { best = ob; bidx = oi; }
        }
        if (l == 0 && anym) {
            acc += fmaxf(0.0f, dij - sdist[bidx] + MARGIN_F);
            cnt += 1;
        }
    }

    if (l == 0) { wacc[w] = acc; wcnt[w] = cnt; }
    __syncthreads();
    if (t == 0) {
        float a = 0.0f; int c = 0;
#pragma unroll
        for (int q = 0; q < NWARP; q++) { a += wacc[q]; c += wcnt[q]; }
        g_bsum[i] = a; g_bcnt[i] = c;
        __threadfence();
        const int v = atomicAdd(&g_arrive, 1);
        slast = (v == BB - 1);
    }
    __syncthreads();

    // last CTA performs the deterministic fixed-order final reduction
    if (slast) {
        __threadfence();   // acquire: make all CTAs' g_bsum/g_bcnt visible
        __shared__ float ss[512];
        __shared__ int   sc2[512];
        ss[t]  = g_bsum[t];
        sc2[t] = g_bcnt[t];
        ss[t + 256]  = (t + 256 < BB) ? g_bsum[t + 256] : 0.0f;
        sc2[t + 256] = (t + 256 < BB) ? g_bcnt[t + 256] : 0;
        __syncthreads();
#pragma unroll
        for (int o = 256; o > 0; o >>= 1) {
            if (t < o) { ss[t] += ss[t + o]; sc2[t] += sc2[t + o]; }
            __syncthreads();
        }
        if (t == 0) {
            out[0] = (sc2[0] > 0) ? (ss[0] / (float)sc2[0]) : 0.0f;
            g_arrive = 0;   // reset for next graph replay
        }
    }
}

extern "C" void kernel_launch(void* const* d_in, const int* in_sizes, int n_in,
                              void* d_out, int out_size)
{
    const float* feat   = (const float*)d_in[0];
    const int*   labels = (const int*)d_in[1];
    const int*   epoch  = (const int*)d_in[2];
    float*       out    = (float*)d_out;
    (void)in_sizes; (void)n_in; (void)out_size;

    dist_kernel<<<dim3(BB / NWARP, 3), 256>>>(feat);
    pair_kernel<<<BB, 256>>>(labels, epoch, out);
}